// round 16
// baseline (speedup 1.0000x reference)
#include <cuda_runtime.h>
#include <math.h>

// ============================================================================
// ResidualGraph: B=4096, C=62, F_IN=256, OUT=BN=64, topK=10
//
// kernel 1 (proj): unchanged from R15 (merged prep; BK=32; broadcast B).
// kernel 2 (graph): v3 smem-traffic cut:
//   - layer GEMM: warp = (rg, s-half), lane owns 2 cols -> h broadcasts halved
//   - agg: float2 column pairs; residual RMW as one aligned float4
//   - A2: 8 rows per warp in a single k loop
// ============================================================================

#define PSZ_ ((size_t)253952 * 64)     // elems per projection matrix

// scratch: [m][row][64], m in {mask, xa, xr, xroot}
__device__ float g_P[4 * 253952 * 64];

typedef unsigned long long ull;

// duplicated mid weights: ull index = ((Lm*32 + kk)*64 + col)*2 + (k&1)
__device__ __align__(16) ull g_Wdup[12 * 32 * 64 * 2];

// ---------------- f32x2 packed-FMA helpers (Blackwell FFMA2) ----------------
__device__ __forceinline__ ull pk(float x, float y) {
    ull r;
    asm("mov.b64 %0, {%1, %2};" : "=l"(r)
        : "r"(__float_as_uint(x)), "r"(__float_as_uint(y)));
    return r;
}
__device__ __forceinline__ float2 upk(ull p) {
    unsigned lo, hi;
    asm("mov.b64 {%0, %1}, %2;" : "=r"(lo), "=r"(hi) : "l"(p));
    return make_float2(__uint_as_float(lo), __uint_as_float(hi));
}
__device__ __forceinline__ ull f2(ull a, ull b, ull c) {
    ull d;
    asm("fma.rn.f32x2 %0, %1, %2, %3;" : "=l"(d) : "l"(a), "l"(b), "l"(c));
    return d;
}

// ============================================================================
// Kernel 1: projections + merged prep. grid = (4, 1985), 256 threads.
// (byte-identical to the R15 passing build)
// ============================================================================
__global__ __launch_bounds__(256, 3) void proj_kernel(
    const float* __restrict__ X,
    const float* __restrict__ Wg, const float* __restrict__ Wb,
    const float* __restrict__ Wr, const float* __restrict__ Wo,
    const float* __restrict__ gb, const float* __restrict__ bb,
    const float* __restrict__ wrel_mid, const float* __restrict__ wroot_mid)
{
    __shared__ __align__(16) float As[32 * 132];   // As[k][row], pitch 132
    __shared__ __align__(16) ull   Bs[32 * 64];    // Bs[k][col] duplicated

    const int tid = threadIdx.x;
    const int m   = blockIdx.x;

    if (blockIdx.y == 1984) {
        int i = (m * 256 + tid) * 48;
        for (int e = 0; e < 48; e++, i++) {
            const int Lm  = i >> 12;
            const int rem = i & 4095;
            const int k   = rem >> 6;
            const int col = rem & 63;
            const int L   = Lm >> 1;
            const float w = (Lm & 1) ? wroot_mid[L * 4096 + k * 64 + col]
                                     : wrel_mid [L * 4096 + k * 64 + col];
            g_Wdup[(((size_t)Lm * 32 + (k >> 1)) * 64 + col) * 2 + (k & 1)] =
                pk(w, w);
        }
        return;
    }

    const float* W = (m == 0) ? Wg : (m == 1) ? Wb : (m == 2) ? Wr : Wo;

    const int lane = tid & 31, wrp = tid >> 5;
    const size_t rowBase = (size_t)blockIdx.y * 128;

    const int ar = tid >> 1;
    const int ak = (tid & 1) * 16;
    const int bk = tid >> 3;
    const int bq = tid & 7;
    const float* Ag = X + (rowBase + ar) * 256 + ak;
    const float* Bg = W + bk * 64 + bq * 8;

    ull acc[2][8];
#pragma unroll
    for (int rp = 0; rp < 2; rp++)
#pragma unroll
        for (int c = 0; c < 8; c++) acc[rp][c] = 0ull;

    float4 av0 = *(const float4*)(Ag);
    float4 av1 = *(const float4*)(Ag + 4);
    float4 av2 = *(const float4*)(Ag + 8);
    float4 av3 = *(const float4*)(Ag + 12);
    float4 bv0 = *(const float4*)(Bg);
    float4 bv1 = *(const float4*)(Bg + 4);

    for (int k0 = 0; k0 < 256; k0 += 32) {
        __syncthreads();
        As[(ak + 0)  * 132 + ar] = av0.x;
        As[(ak + 1)  * 132 + ar] = av0.y;
        As[(ak + 2)  * 132 + ar] = av0.z;
        As[(ak + 3)  * 132 + ar] = av0.w;
        As[(ak + 4)  * 132 + ar] = av1.x;
        As[(ak + 5)  * 132 + ar] = av1.y;
        As[(ak + 6)  * 132 + ar] = av1.z;
        As[(ak + 7)  * 132 + ar] = av1.w;
        As[(ak + 8)  * 132 + ar] = av2.x;
        As[(ak + 9)  * 132 + ar] = av2.y;
        As[(ak + 10) * 132 + ar] = av2.z;
        As[(ak + 11) * 132 + ar] = av2.w;
        As[(ak + 12) * 132 + ar] = av3.x;
        As[(ak + 13) * 132 + ar] = av3.y;
        As[(ak + 14) * 132 + ar] = av3.z;
        As[(ak + 15) * 132 + ar] = av3.w;
        {
            ull* bd = Bs + bk * 64 + bq * 8;
            bd[0] = pk(bv0.x, bv0.x);
            bd[1] = pk(bv0.y, bv0.y);
            bd[2] = pk(bv0.z, bv0.z);
            bd[3] = pk(bv0.w, bv0.w);
            bd[4] = pk(bv1.x, bv1.x);
            bd[5] = pk(bv1.y, bv1.y);
            bd[6] = pk(bv1.z, bv1.z);
            bd[7] = pk(bv1.w, bv1.w);
        }
        __syncthreads();
        if (k0 + 32 < 256) {
            av0 = *(const float4*)(Ag + k0 + 32);
            av1 = *(const float4*)(Ag + k0 + 36);
            av2 = *(const float4*)(Ag + k0 + 40);
            av3 = *(const float4*)(Ag + k0 + 44);
            bv0 = *(const float4*)(Bg + (k0 + 32) * 64);
            bv1 = *(const float4*)(Bg + (k0 + 32) * 64 + 4);
        }
#pragma unroll
        for (int k = 0; k < 32; k++) {
            ulonglong2 a2 = *(const ulonglong2*)(As + k * 132 + lane * 4);
            const ull* bp = Bs + k * 64 + wrp * 8;
            ulonglong2 b01 = *(const ulonglong2*)(bp);
            ulonglong2 b23 = *(const ulonglong2*)(bp + 2);
            ulonglong2 b45 = *(const ulonglong2*)(bp + 4);
            ulonglong2 b67 = *(const ulonglong2*)(bp + 6);
            acc[0][0] = f2(a2.x, b01.x, acc[0][0]);
            acc[0][1] = f2(a2.x, b01.y, acc[0][1]);
            acc[0][2] = f2(a2.x, b23.x, acc[0][2]);
            acc[0][3] = f2(a2.x, b23.y, acc[0][3]);
            acc[0][4] = f2(a2.x, b45.x, acc[0][4]);
            acc[0][5] = f2(a2.x, b45.y, acc[0][5]);
            acc[0][6] = f2(a2.x, b67.x, acc[0][6]);
            acc[0][7] = f2(a2.x, b67.y, acc[0][7]);
            acc[1][0] = f2(a2.y, b01.x, acc[1][0]);
            acc[1][1] = f2(a2.y, b01.y, acc[1][1]);
            acc[1][2] = f2(a2.y, b23.x, acc[1][2]);
            acc[1][3] = f2(a2.y, b23.y, acc[1][3]);
            acc[1][4] = f2(a2.y, b45.x, acc[1][4]);
            acc[1][5] = f2(a2.y, b45.y, acc[1][5]);
            acc[1][6] = f2(a2.y, b67.x, acc[1][6]);
            acc[1][7] = f2(a2.y, b67.y, acc[1][7]);
        }
    }

    float bia[8];
#pragma unroll
    for (int c = 0; c < 8; c++) bia[c] = 0.f;
    if (m == 0) {
        float4 t0 = *(const float4*)(gb + wrp * 8);
        float4 t1 = *(const float4*)(gb + wrp * 8 + 4);
        bia[0] = t0.x; bia[1] = t0.y; bia[2] = t0.z; bia[3] = t0.w;
        bia[4] = t1.x; bia[5] = t1.y; bia[6] = t1.z; bia[7] = t1.w;
    } else if (m == 1) {
        float4 t0 = *(const float4*)(bb + wrp * 8);
        float4 t1 = *(const float4*)(bb + wrp * 8 + 4);
        bia[0] = t0.x; bia[1] = t0.y; bia[2] = t0.z; bia[3] = t0.w;
        bia[4] = t1.x; bia[5] = t1.y; bia[6] = t1.z; bia[7] = t1.w;
    }

    float* Pm = g_P + (size_t)m * PSZ_ + rowBase * 64;
#pragma unroll
    for (int rp = 0; rp < 2; rp++) {
        float2 c0 = upk(acc[rp][0]), c1 = upk(acc[rp][1]);
        float2 c2 = upk(acc[rp][2]), c3 = upk(acc[rp][3]);
        float2 c4 = upk(acc[rp][4]), c5 = upk(acc[rp][5]);
        float2 c6 = upk(acc[rp][6]), c7 = upk(acc[rp][7]);
#pragma unroll
        for (int j = 0; j < 2; j++) {
            const int row = lane * 4 + rp * 2 + j;
            float4 lo, hi;
            lo.x = j ? c0.y : c0.x;  lo.y = j ? c1.y : c1.x;
            lo.z = j ? c2.y : c2.x;  lo.w = j ? c3.y : c3.x;
            hi.x = j ? c4.y : c4.x;  hi.y = j ? c5.y : c5.x;
            hi.z = j ? c6.y : c6.x;  hi.w = j ? c7.y : c7.x;
            if (m < 2) {
                lo.x = tanhf(lo.x + bia[0]); lo.y = tanhf(lo.y + bia[1]);
                lo.z = tanhf(lo.z + bia[2]); lo.w = tanhf(lo.w + bia[3]);
                hi.x = tanhf(hi.x + bia[4]); hi.y = tanhf(hi.y + bia[5]);
                hi.z = tanhf(hi.z + bia[6]); hi.w = tanhf(hi.w + bia[7]);
            }
            float* dst = Pm + (size_t)row * 64 + wrp * 8;
            *(float4*)(dst)     = lo;
            *(float4*)(dst + 4) = hi;
        }
    }
}

// ============================================================================
// Kernel 2: per-batch graph phase. grid = 4096 CTAs x 256 threads.
// Paired h layout: H(r,c) = ((r&3)*8 + (r>>3))*128 + c*2 + ((r>>2)&1)
// ============================================================================
#define HIDX(r, c) ((((r) & 3) * 8 + ((r) >> 3)) * 128 + (c) * 2 + (((r) >> 2) & 1))

__global__ __launch_bounds__(256, 3) void graph_kernel(
    const float* __restrict__ brel_mid,
    const float* __restrict__ relb1,
    float* __restrict__ out)
{
    __shared__ __align__(16) float  s_h[4096];
    __shared__ __align__(16) float  s_hr[4160];
    __shared__ __align__(16) float2 s_tk[620];

    const int tid = threadIdx.x;
    const size_t base = (size_t)blockIdx.x * 3968;

    const float* P0 = g_P;                 // x_mask
    const float* P1 = g_P + PSZ_;          // xa
    const float* P2 = g_P + 2 * PSZ_;      // xr
    const float* P3 = g_P + 3 * PSZ_;      // xroot

    // ---- Phase A1: load xa plain (s_h) + transposed pitch-65 (s_hr) ----
    {
        const float* gxa = P1 + base;
        for (int i = tid; i < 3968; i += 256) {
            float v = gxa[i];
            s_h[i] = v;
            s_hr[(i & 63) * 65 + (i >> 6)] = v;
        }
        if (tid < 128) s_h[3968 + tid] = 0.f;   // rows 62/63 read by A2 warp 7
    }
    __syncthreads();

    // ---- Phase A2: logits + softmax + top-10 (warp per 8 rows) ----
    {
        const int warp = tid >> 5, lane = tid & 31;
        const unsigned FULL = 0xFFFFFFFFu;
        const int rb = warp * 8;
        float ac[8][2];
#pragma unroll
        for (int j = 0; j < 8; j++) { ac[j][0] = 0.f; ac[j][1] = 0.f; }
        const float* xa = s_h + rb * 64;
#pragma unroll 4
        for (int k = 0; k < 64; k++) {
            const float c0 = s_hr[k * 65 + lane];
            const float c1 = s_hr[k * 65 + lane + 32];
#pragma unroll
            for (int j = 0; j < 8; j++) {
                const float x = xa[j * 64 + k];
                ac[j][0] = fmaf(x, c0, ac[j][0]);
                ac[j][1] = fmaf(x, c1, ac[j][1]);
            }
        }
        const bool v1ok = (lane + 32) < 62;
#pragma unroll
        for (int j = 0; j < 8; j++) {
            const int r = rb + j;
            if (r >= 62) break;
            float l0 = ac[j][0];
            float l1 = v1ok ? ac[j][1] : -1e30f;
            float mx = fmaxf(l0, l1);
#pragma unroll
            for (int s = 16; s; s >>= 1)
                mx = fmaxf(mx, __shfl_xor_sync(FULL, mx, s));
            float e0 = __expf(l0 - mx);
            float e1 = v1ok ? __expf(l1 - mx) : 0.f;
            float sm = e0 + e1;
#pragma unroll
            for (int s = 16; s; s >>= 1)
                sm += __shfl_xor_sync(FULL, sm, s);
            const float inv = 1.f / sm;
            float p0 = e0 * inv;
            float p1 = e1 * inv;   // invalid lanes: exactly 0
            for (int t = 0; t < 10; t++) {
                unsigned u0 = __float_as_uint(p0);
                unsigned u1 = __float_as_uint(p1);
                unsigned mb = u0 > u1 ? u0 : u1;
                unsigned best = __reduce_max_sync(FULL, mb);
                unsigned m0 = __ballot_sync(FULL, u0 == best);
                unsigned m1 = __ballot_sync(FULL, u1 == best);
                int widx = m0 ? (__ffs(m0) - 1) : (__ffs(m1) - 1 + 32);
                if (lane == 0)
                    s_tk[r * 10 + t] =
                        make_float2(__uint_as_float(best), __int_as_float(widx));
                if (widx == lane)            p0 = 0.f;
                else if (widx == lane + 32)  p1 = 0.f;
            }
        }
    }
    __syncthreads();

    // ---- stage xr into s_hr (plain [62][64]); zero tail (rows 62/63) ----
    {
        const float4* gxr = (const float4*)(P2 + base);
        float4* dst = (float4*)s_hr;
        for (int i = tid; i < 992; i += 256) dst[i] = gxr[i];
        if (tid < 48)
            dst[992 + tid] = make_float4(0.f, 0.f, 0.f, 0.f);
    }
    __syncthreads();

    // ---- Layer 1: h = relu(agg(xr) + rel_b1 + xroot), write paired s_h ----
    {
        const int rg  = tid >> 6;
        const int col = tid & 63;
        const float bi = relb1[col];
        const float* gxo = P3 + base;
        if (tid < 64) {  // zero pad rows 62/63
            s_h[HIDX(62, tid)] = 0.f;
            s_h[HIDX(63, tid)] = 0.f;
        }
#pragma unroll
        for (int t = 0; t < 16; t++) {
            const int r = rg + 4 * t;
            if (r < 62) {
                float aa = bi + gxo[r * 64 + col];
                float ab = 0.f;
                const float2* tk = s_tk + r * 10;
#pragma unroll
                for (int u = 0; u < 10; u += 2) {
                    float2 e0 = tk[u], e1 = tk[u + 1];
                    aa = fmaf(e0.x, s_hr[__float_as_int(e0.y) * 64 + col], aa);
                    ab = fmaf(e1.x, s_hr[__float_as_int(e1.y) * 64 + col], ab);
                }
                s_h[HIDX(r, col)] = fmaxf(aa + ab, 0.f);
            }
        }
    }
    __syncthreads();

    // ---- Layers 2..7: warp = (rg, s-half); lane owns cols 2l, 2l+1 ----
    const int lane = tid & 31, w = tid >> 5;
    const int rgp = w >> 1;            // pair-layout rg
    const int sh  = (w & 1) * 4;       // s offset: 0 or 4
    const int c0  = lane * 2;
    const int pbW = rgp * 1024 + sh * 128;
    const float2 br2base = make_float2(0.f, 0.f); (void)br2base;

    for (int L = 0; L < 6; L++) {
        const ulonglong2* WDr =
            (const ulonglong2*)g_Wdup + ((size_t)(L * 2 + 0) * 32) * 64 + c0;
        const ulonglong2* WDo =
            (const ulonglong2*)g_Wdup + ((size_t)(L * 2 + 1) * 32) * 64 + c0;

        ull aR[4][2], aO[4][2];
#pragma unroll
        for (int s = 0; s < 4; s++) {
            aR[s][0] = 0ull; aR[s][1] = 0ull;
            aO[s][0] = 0ull; aO[s][1] = 0ull;
        }

#pragma unroll 2
        for (int kk = 0; kk < 32; kk++) {
            const ulonglong2 wr0 = WDr[kk * 64];
            const ulonglong2 wr1 = WDr[kk * 64 + 1];
            const ulonglong2 wo0 = WDo[kk * 64];
            const ulonglong2 wo1 = WDo[kk * 64 + 1];
            const float* hp = s_h + pbW + kk * 4;
            const ulonglong2 h0 = *(const ulonglong2*)(hp);
            const ulonglong2 h1 = *(const ulonglong2*)(hp + 128);
            const ulonglong2 h2 = *(const ulonglong2*)(hp + 256);
            const ulonglong2 h3 = *(const ulonglong2*)(hp + 384);
            aR[0][0] = f2(h0.x, wr0.x, aR[0][0]);
            aR[0][0] = f2(h0.y, wr0.y, aR[0][0]);
            aR[0][1] = f2(h0.x, wr1.x, aR[0][1]);
            aR[0][1] = f2(h0.y, wr1.y, aR[0][1]);
            aO[0][0] = f2(h0.x, wo0.x, aO[0][0]);
            aO[0][0] = f2(h0.y, wo0.y, aO[0][0]);
            aO[0][1] = f2(h0.x, wo1.x, aO[0][1]);
            aO[0][1] = f2(h0.y, wo1.y, aO[0][1]);
            aR[1][0] = f2(h1.x, wr0.x, aR[1][0]);
            aR[1][0] = f2(h1.y, wr0.y, aR[1][0]);
            aR[1][1] = f2(h1.x, wr1.x, aR[1][1]);
            aR[1][1] = f2(h1.y, wr1.y, aR[1][1]);
            aO[1][0] = f2(h1.x, wo0.x, aO[1][0]);
            aO[1][0] = f2(h1.y, wo0.y, aO[1][0]);
            aO[1][1] = f2(h1.x, wo1.x, aO[1][1]);
            aO[1][1] = f2(h1.y, wo1.y, aO[1][1]);
            aR[2][0] = f2(h2.x, wr0.x, aR[2][0]);
            aR[2][0] = f2(h2.y, wr0.y, aR[2][0]);
            aR[2][1] = f2(h2.x, wr1.x, aR[2][1]);
            aR[2][1] = f2(h2.y, wr1.y, aR[2][1]);
            aO[2][0] = f2(h2.x, wo0.x, aO[2][0]);
            aO[2][0] = f2(h2.y, wo0.y, aO[2][0]);
            aO[2][1] = f2(h2.x, wo1.x, aO[2][1]);
            aO[2][1] = f2(h2.y, wo1.y, aO[2][1]);
            aR[3][0] = f2(h3.x, wr0.x, aR[3][0]);
            aR[3][0] = f2(h3.y, wr0.y, aR[3][0]);
            aR[3][1] = f2(h3.x, wr1.x, aR[3][1]);
            aR[3][1] = f2(h3.y, wr1.y, aR[3][1]);
            aO[3][0] = f2(h3.x, wo0.x, aO[3][0]);
            aO[3][0] = f2(h3.y, wo0.y, aO[3][0]);
            aO[3][1] = f2(h3.x, wo1.x, aO[3][1]);
            aO[3][1] = f2(h3.y, wo1.y, aO[3][1]);
        }

        // hr -> smem plain layout (float2: both cols at once)
#pragma unroll
        for (int s = 0; s < 4; s++) {
            float2 v0 = upk(aR[s][0]);          // (r0,c0),(r1,c0)
            float2 v1 = upk(aR[s][1]);          // (r0,c1),(r1,c1)
            const int r0 = rgp + 8 * (sh + s);
            *(float2*)(s_hr + r0 * 64 + c0)       = make_float2(v0.x, v1.x);
            *(float2*)(s_hr + (r0 + 4) * 64 + c0) = make_float2(v0.y, v1.y);
        }
        __syncthreads();

        // sparse aggregation + bias + root + relu (+ residual / final output)
        const float2 br2 = *(const float2*)(brel_mid + L * 64 + c0);
        const bool last = (L == 5);
#pragma unroll
        for (int s = 0; s < 4; s++) {
            const int r0 = rgp + 8 * (sh + s);   // < 60 always
            const int r1 = r0 + 4;
            const int pbase = (rgp * 8 + sh + s) * 128;
            float2 o0 = upk(aO[s][0]);           // root: (r0,c0),(r1,c0)
            float2 o1 = upk(aO[s][1]);
            // row r0 (always valid)
            float aa0 = br2.x + o0.x, ab0 = 0.f;
            float aa1 = br2.y + o1.x, ab1 = 0.f;
            {
                const float2* tk = s_tk + r0 * 10;
#pragma unroll
                for (int u = 0; u < 10; u += 2) {
                    float2 e0 = tk[u], e1 = tk[u + 1];
                    float2 hv0 = *(const float2*)(s_hr + __float_as_int(e0.y) * 64 + c0);
                    float2 hv1 = *(const float2*)(s_hr + __float_as_int(e1.y) * 64 + c0);
                    aa0 = fmaf(e0.x, hv0.x, aa0);
                    aa1 = fmaf(e0.x, hv0.y, aa1);
                    ab0 = fmaf(e1.x, hv1.x, ab0);
                    ab1 = fmaf(e1.x, hv1.y, ab1);
                }
            }
            const float vr0c0 = fmaxf(aa0 + ab0, 0.f);
            const float vr0c1 = fmaxf(aa1 + ab1, 0.f);

            if (r1 < 62) {
                float ba0 = br2.x + o0.y, bb0 = 0.f;
                float ba1 = br2.y + o1.y, bb1 = 0.f;
                const float2* tk = s_tk + r1 * 10;
#pragma unroll
                for (int u = 0; u < 10; u += 2) {
                    float2 e0 = tk[u], e1 = tk[u + 1];
                    float2 hv0 = *(const float2*)(s_hr + __float_as_int(e0.y) * 64 + c0);
                    float2 hv1 = *(const float2*)(s_hr + __float_as_int(e1.y) * 64 + c0);
                    ba0 = fmaf(e0.x, hv0.x, ba0);
                    ba1 = fmaf(e0.x, hv0.y, ba1);
                    bb0 = fmaf(e1.x, hv1.x, bb0);
                    bb1 = fmaf(e1.x, hv1.y, bb1);
                }
                const float vr1c0 = fmaxf(ba0 + bb0, 0.f);
                const float vr1c1 = fmaxf(ba1 + bb1, 0.f);
                if (last) {
                    float2 m0 = *(const float2*)(P0 + base + r0 * 64 + c0);
                    float2 m1 = *(const float2*)(P0 + base + r1 * 64 + c0);
                    *(float2*)(out + base + r0 * 64 + c0) =
                        make_float2(vr0c0 * m0.x, vr0c1 * m0.y);
                    *(float2*)(out + base + r1 * 64 + c0) =
                        make_float2(vr1c0 * m1.x, vr1c1 * m1.y);
                } else {
                    float4* hq = (float4*)(s_h + pbase + lane * 4);
                    float4 f = *hq;              // (r0,c0)(r1,c0)(r0,c1)(r1,c1)
                    f.x += vr0c0; f.y += vr1c0;
                    f.z += vr0c1; f.w += vr1c1;
                    *hq = f;
                }
            } else {   // r1 == 62/63: only r0 contributes
                if (last) {
                    float2 m0 = *(const float2*)(P0 + base + r0 * 64 + c0);
                    *(float2*)(out + base + r0 * 64 + c0) =
                        make_float2(vr0c0 * m0.x, vr0c1 * m0.y);
                } else {
                    s_h[pbase + lane * 4]     += vr0c0;
                    s_h[pbase + lane * 4 + 2] += vr0c1;
                }
            }
        }
        __syncthreads();
    }
}

// ============================================================================
// launch
// ============================================================================
extern "C" void kernel_launch(void* const* d_in, const int* in_sizes, int n_in,
                              void* d_out, int out_size) {
    const float* x        = (const float*)d_in[0];
    const float* gate_w   = (const float*)d_in[1];
    const float* gate_b   = (const float*)d_in[2];
    const float* bnlin_w  = (const float*)d_in[3];
    const float* bnlin_b  = (const float*)d_in[4];
    const float* rel_w1   = (const float*)d_in[5];
    const float* rel_b1   = (const float*)d_in[6];
    const float* root_w1  = (const float*)d_in[7];
    const float* rel_w_m  = (const float*)d_in[8];
    const float* rel_b_m  = (const float*)d_in[9];
    const float* root_w_m = (const float*)d_in[10];
    float* out = (float*)d_out;

    proj_kernel<<<dim3(4, 1985), 256>>>(x, gate_w, bnlin_w, rel_w1, root_w1,
                                        gate_b, bnlin_b, rel_w_m, root_w_m);
    graph_kernel<<<4096, 256>>>(rel_b_m, rel_b1, out);
}